// round 1
// baseline (speedup 1.0000x reference)
#include <cuda_runtime.h>
#include <cuda_bf16.h>

// y[b] = sum_{s=0}^{21} w[s] * f_s(x[b,:]) where f_s picks, in priority m=2,1,0,
// the first m with l=s-3m in [0,16) and d = x[b,m]-phis[m,l] in (-iv[m], iv[m]],
// giving 0.5*cos(d)+0.5 (else 0). Output: [y (batch floats), weight (48 floats)].

#define TPB 256
#define ROWS_PER_THREAD 4

__device__ __forceinline__ float row_eval(float x0, float x1, float x2,
                                          const float* __restrict__ sp,
                                          const float* __restrict__ siv,
                                          const float* __restrict__ sw) {
    float xm0 = x0, xm1 = x1, xm2 = x2;
    float y = 0.0f;
#pragma unroll
    for (int s = 0; s < 22; ++s) {
        float dsel = 0.0f;
        bool found = false;
        // priority: m = 2, then 1, then 0 (higher j wins the segment_max)
#pragma unroll
        for (int mm = 2; mm >= 0; --mm) {
            const int l = s - 3 * mm;
            if (l >= 0 && l < 16) {
                const float xv  = (mm == 0) ? xm0 : (mm == 1 ? xm1 : xm2);
                const float d   = xv - sp[mm * 16 + l];
                const float iv  = siv[mm];
                const bool  c   = (d > -iv) && (d <= iv);
                if (c && !found) { dsel = d; found = true; }
            }
        }
        if (found) {
            y += (0.5f * __cosf(dsel) + 0.5f) * sw[s];
        }
    }
    return y;
}

__global__ void __launch_bounds__(TPB)
glm_kernel(const float* __restrict__ x,
           const float* __restrict__ phis,
           const float* __restrict__ interval,
           const float* __restrict__ weight,
           float* __restrict__ out,
           int batch) {
    __shared__ float sp[48];
    __shared__ float siv[3];
    __shared__ float sw[22];

    const int t = threadIdx.x;
    if (t < 48) sp[t] = phis[t];
    if (t < 3)  siv[t] = interval[t];
    if (t < 22) sw[t] = weight[t];

    // tail: copy weight (48 floats) after the batch of y values
    if (blockIdx.x == 0 && t < 48) {
        out[batch + t] = weight[t];
    }
    __syncthreads();

    const int tid = blockIdx.x * TPB + t;
    const long long r0 = (long long)tid * ROWS_PER_THREAD;
    if (r0 >= batch) return;

    // 4 rows * 3 floats = 48 bytes = 3 x float4, 16B-aligned (r0 % 4 == 0)
    const float4* xv = reinterpret_cast<const float4*>(x + r0 * 3);
    const float4 a = xv[0];
    const float4 b = xv[1];
    const float4 c = xv[2];

    float4 yo;
    yo.x = row_eval(a.x, a.y, a.z, sp, siv, sw);
    yo.y = row_eval(a.w, b.x, b.y, sp, siv, sw);
    yo.z = row_eval(b.z, b.w, c.x, sp, siv, sw);
    yo.w = row_eval(c.y, c.z, c.w, sp, siv, sw);

    reinterpret_cast<float4*>(out)[tid] = yo;
}

extern "C" void kernel_launch(void* const* d_in, const int* in_sizes, int n_in,
                              void* d_out, int out_size) {
    const float* x        = (const float*)d_in[0];
    const float* phis     = (const float*)d_in[1];
    const float* interval = (const float*)d_in[2];
    const float* weight   = (const float*)d_in[3];
    float* out = (float*)d_out;

    const int batch = in_sizes[0] / 3;  // x is (batch, 3)
    const int n_threads = (batch + ROWS_PER_THREAD - 1) / ROWS_PER_THREAD;
    const int n_blocks  = (n_threads + TPB - 1) / TPB;

    glm_kernel<<<n_blocks, TPB>>>(x, phis, interval, weight, out, batch);
}

// round 2
// speedup vs baseline: 1.1952x; 1.1952x over previous
#include <cuda_runtime.h>
#include <cuda_bf16.h>

// y[b] = sum_{s=0}^{21} w[s] * f_s(x[b,:]).
// Segment s has candidates (m, l=s-3m) for m with l in [0,16); priority = largest m.
// Candidate valid iff x[m] in (phi-iv[m], phi+iv[m]]  (== diff in (-iv, iv]).
// f_s = 0.5*cos(x[m*]-phi*) + 0.5 for the selected candidate, else 0.
// Output layout: [ y (batch floats) , weight (48 floats) ].

#define TPB 256
#define RPT 4

__device__ __forceinline__ void acc1(float xa, float phia, float loa, float hia,
                                     float hw, float& y) {
    const bool  pa = (xa > loa) && (xa <= hia);
    const float w  = pa ? hw : 0.0f;
    const float d  = xa - phia;
    y += w * (__cosf(d) + 1.0f);
}

__device__ __forceinline__ void acc2(float xa, float phia, float loa, float hia,
                                     float xb, float phib, float lob, float hib,
                                     float hw, float& y) {
    const bool  pa = (xa > loa) && (xa <= hia);   // higher-m candidate (priority)
    const bool  pb = (xb > lob) && (xb <= hib);
    const float da = xa - phia;
    const float db = xb - phib;
    const float d  = pa ? da : db;
    const float w  = (pa || pb) ? hw : 0.0f;
    y += w * (__cosf(d) + 1.0f);
}

__device__ __forceinline__ void acc3(float xa, float phia, float loa, float hia,
                                     float xb, float phib, float lob, float hib,
                                     float xc, float phic, float loc, float hic,
                                     float hw, float& y) {
    const bool  pa = (xa > loa) && (xa <= hia);   // m=2 (highest priority)
    const bool  pb = (xb > lob) && (xb <= hib);   // m=1
    const bool  pc = (xc > loc) && (xc <= hic);   // m=0
    const float da = xa - phia;
    const float db = xb - phib;
    const float dc = xc - phic;
    float d = pb ? db : dc;
    d = pa ? da : d;
    const float w  = (pa || pb || pc) ? hw : 0.0f;
    y += w * (__cosf(d) + 1.0f);
}

__global__ void __launch_bounds__(TPB, 4)
glm_kernel(const float* __restrict__ x,
           const float* __restrict__ phis,
           const float* __restrict__ interval,
           const float* __restrict__ weight,
           float* __restrict__ out,
           int batch) {
    __shared__ float sphi[48];
    __shared__ float slo[48];
    __shared__ float shi[48];
    __shared__ float shw[22];

    const int t = threadIdx.x;
    if (t < 48) {
        const int   m  = t >> 4;
        const float p  = phis[t];
        const float iv = interval[m];
        sphi[t] = p;
        slo[t]  = p - iv;   // x > lo  <=>  diff > -iv
        shi[t]  = p + iv;   // x <= hi <=>  diff <= iv
    }
    if (t < 22) shw[t] = 0.5f * weight[t];
    if (blockIdx.x == 0 && t < 48) out[batch + t] = weight[t];  // tail: weight copy
    __syncthreads();

    const int tid = blockIdx.x * TPB + t;
    const long long r0 = (long long)tid * RPT;
    if (r0 >= batch) return;

    // 4 rows * 3 floats = 48B = 3 x float4 (16B aligned since r0 % 4 == 0)
    const float4* xv = reinterpret_cast<const float4*>(x + r0 * 3);
    const float4 va = xv[0];
    const float4 vb = xv[1];
    const float4 vc = xv[2];

    float xr[RPT][3] = {
        {va.x, va.y, va.z},
        {va.w, vb.x, vb.y},
        {vb.z, vb.w, vc.x},
        {vc.y, vc.z, vc.w}
    };
    float y[RPT] = {0.0f, 0.0f, 0.0f, 0.0f};

    // s = 0..2 : only m=0, l=s
#pragma unroll
    for (int s = 0; s < 3; ++s) {
        const int ca = s;
        const float pA = sphi[ca], lA = slo[ca], hA = shi[ca], hw = shw[s];
#pragma unroll
        for (int r = 0; r < RPT; ++r)
            acc1(xr[r][0], pA, lA, hA, hw, y[r]);
    }

    // s = 3..5 : m=1 (pri), m=0
#pragma unroll
    for (int s = 3; s < 6; ++s) {
        const int ca = 16 + (s - 3);
        const int cb = s;
        const float pA = sphi[ca], lA = slo[ca], hA = shi[ca];
        const float pB = sphi[cb], lB = slo[cb], hB = shi[cb];
        const float hw = shw[s];
#pragma unroll
        for (int r = 0; r < RPT; ++r)
            acc2(xr[r][1], pA, lA, hA, xr[r][0], pB, lB, hB, hw, y[r]);
    }

    // s = 6..15 : m=2 (pri), m=1, m=0
#pragma unroll
    for (int s = 6; s < 16; ++s) {
        const int ca = 32 + (s - 6);
        const int cb = 16 + (s - 3);
        const int cc = s;
        const float pA = sphi[ca], lA = slo[ca], hA = shi[ca];
        const float pB = sphi[cb], lB = slo[cb], hB = shi[cb];
        const float pC = sphi[cc], lC = slo[cc], hC = shi[cc];
        const float hw = shw[s];
#pragma unroll
        for (int r = 0; r < RPT; ++r)
            acc3(xr[r][2], pA, lA, hA,
                 xr[r][1], pB, lB, hB,
                 xr[r][0], pC, lC, hC, hw, y[r]);
    }

    // s = 16..18 : m=2 (pri), m=1
#pragma unroll
    for (int s = 16; s < 19; ++s) {
        const int ca = 32 + (s - 6);
        const int cb = 16 + (s - 3);
        const float pA = sphi[ca], lA = slo[ca], hA = shi[ca];
        const float pB = sphi[cb], lB = slo[cb], hB = shi[cb];
        const float hw = shw[s];
#pragma unroll
        for (int r = 0; r < RPT; ++r)
            acc2(xr[r][2], pA, lA, hA, xr[r][1], pB, lB, hB, hw, y[r]);
    }

    // s = 19..21 : only m=2, l=s-6
#pragma unroll
    for (int s = 19; s < 22; ++s) {
        const int ca = 32 + (s - 6);
        const float pA = sphi[ca], lA = slo[ca], hA = shi[ca], hw = shw[s];
#pragma unroll
        for (int r = 0; r < RPT; ++r)
            acc1(xr[r][2], pA, lA, hA, hw, y[r]);
    }

    float4 yo = make_float4(y[0], y[1], y[2], y[3]);
    reinterpret_cast<float4*>(out)[tid] = yo;
}

extern "C" void kernel_launch(void* const* d_in, const int* in_sizes, int n_in,
                              void* d_out, int out_size) {
    const float* x        = (const float*)d_in[0];
    const float* phis     = (const float*)d_in[1];
    const float* interval = (const float*)d_in[2];
    const float* weight   = (const float*)d_in[3];
    float* out = (float*)d_out;

    const int batch = in_sizes[0] / 3;
    const int n_threads = (batch + RPT - 1) / RPT;
    const int n_blocks  = (n_threads + TPB - 1) / TPB;

    glm_kernel<<<n_blocks, TPB>>>(x, phis, interval, weight, out, batch);
}